// round 9
// baseline (speedup 1.0000x reference)
#include <cuda_runtime.h>
#include <cuda_bf16.h>
#include <cstdint>
#include <mma.h>
#include <math.h>

#define NN 50000
#define EE 800000
#define CC 64
#define SS 10
#define ETILE 256
#define NT (EE / ETILE)   // 3125

typedef unsigned long long ull;
using namespace nvcuda;

// -------- scratch (static device globals; no allocation) --------
__device__ float g_h0[NN * CC];        // up-projected scalars   [n][c]
__device__ float g_h1[NN * 3 * CC];    // up-projected vectors   [n][i][c]
__device__ float g_T0[NN * CC];        // scattered messages (unscaled)
__device__ float g_T1[NN * 3 * CC];
__device__ int   g_deg[NN];
__device__ int   g_off[NN + 1];
__device__ int   g_cur[NN];
__device__ int   g_perm[EE];
__device__ int   g_srcs[EE];           // src per sorted slot
__device__ int   g_dsts[EE];           // dst per sorted slot

// -------- f32x2 packed math helpers --------
__device__ __forceinline__ ull dup2(float x) {
    ull r; asm("mov.b64 %0, {%1, %1};" : "=l"(r) : "r"(__float_as_uint(x)));
    return r;
}
__device__ __forceinline__ void fma2(ull& d, ull a, ull b) {
    asm("fma.rn.f32x2 %0, %1, %2, %0;" : "+l"(d) : "l"(a), "l"(b));
}
__device__ __forceinline__ ull mul2(ull a, ull b) {
    ull d; asm("mul.rn.f32x2 %0, %1, %2;" : "=l"(d) : "l"(a), "l"(b));
    return d;
}
__device__ __forceinline__ void unpack2(ull v, float& lo, float& hi) {
    unsigned int a, b;
    asm("mov.b64 {%0, %1}, %2;" : "=r"(a), "=r"(b) : "l"(v));
    lo = __uint_as_float(a); hi = __uint_as_float(b);
}
__device__ __forceinline__ float segsum(float v, int segs, int lane) {
#pragma unroll
    for (int d = 1; d < 32; d <<= 1) {
        float u = __shfl_up_sync(0xffffffffu, v, d);
        v += (lane - segs >= d) ? u : 0.f;
    }
    return v;
}

// ============================================================
// Zero: T0, T1, deg
// ============================================================
__global__ void zero_kernel() {
    const int i = blockIdx.x * 256 + threadIdx.x;   // 9375*256 = 2.4M
    const float4 z = make_float4(0.f, 0.f, 0.f, 0.f);
    if (i < (NN * CC) / 4)     reinterpret_cast<float4*>(g_T0)[i] = z;
    if (i < (NN * 3 * CC) / 4) reinterpret_cast<float4*>(g_T1)[i] = z;
    if (i < NN)                g_deg[i] = 0;
}

__global__ void hist_kernel(const int* __restrict__ ei) {
    int e = blockIdx.x * 256 + threadIdx.x;
    atomicAdd(&g_deg[ei[EE + e]], 1);
}

__global__ void __launch_bounds__(1024) scan_kernel() {
    __shared__ int sp[1024];
    const int t = threadIdx.x;
    const int CH = (NN + 1023) / 1024;
    const int i0 = t * CH;
    const int i1 = min(i0 + CH, NN);
    int part = 0;
    for (int i = i0; i < i1; i++) part += g_deg[i];
    sp[t] = part;
    __syncthreads();
    for (int off = 1; off < 1024; off <<= 1) {
        int v = (t >= off) ? sp[t - off] : 0;
        __syncthreads();
        sp[t] += v;
        __syncthreads();
    }
    int run = sp[t] - part;
    for (int i = i0; i < i1; i++) {
        g_off[i] = run; g_cur[i] = run; run += g_deg[i];
    }
    if (t == 0) g_off[NN] = EE;
}

__global__ void scatter_kernel(const int* __restrict__ ei) {
    int e = blockIdx.x * 256 + threadIdx.x;
    int s = ei[e], d = ei[EE + e];
    int pos = atomicAdd(&g_cur[d], 1);
    g_perm[pos] = e;
    g_srcs[pos] = s;
    g_dsts[pos] = d;
}

// ============================================================
// Up-projection
// ============================================================
__global__ void __launch_bounds__(256) up_kernel(
    const float* __restrict__ nf0, const float* __restrict__ nf1,
    const float* __restrict__ Wup0, const float* __restrict__ Wup1) {
    extern __shared__ float sm[];
    float* sW0  = sm;
    float* sW1m = sm + 4096;
    float* s0   = sm + 8192;
    float* s1   = sm + 10240;
    const int tid  = threadIdx.x;
    const int base = blockIdx.x * 32;

    for (int i = tid; i < 4096; i += 256) { sW0[i] = Wup0[i]; sW1m[i] = Wup1[i]; }
    for (int i = tid; i < 2048; i += 256) {
        size_t g = (size_t)base * 64 + i;
        s0[i] = (g < (size_t)NN * 64) ? nf0[g] : 0.f;
    }
    for (int i = tid; i < 6144; i += 256) {
        size_t g = (size_t)base * 192 + i;
        s1[i] = (g < (size_t)NN * 192) ? nf1[g] : 0.f;
    }
    __syncthreads();

    const int o = tid & 63, ng = tid >> 6;
    for (int nl = ng; nl < 32; nl += 4) {
        const int n = base + nl;
        if (n >= NN) break;
        float a = 0.f;
#pragma unroll
        for (int c = 0; c < 64; c++) a += s0[nl * 64 + c] * sW0[c * 64 + o];
        g_h0[(size_t)n * 64 + o] = a;
#pragma unroll
        for (int i3 = 0; i3 < 3; i3++) {
            float b = 0.f;
#pragma unroll 16
            for (int c = 0; c < 64; c++)
                b += s1[nl * 192 + c * 3 + i3] * sW1m[c * 64 + o];
            g_h1[((size_t)n * 3 + i3) * 64 + o] = b;
        }
    }
}

// ============================================================
// Edge WMMA kernel: tile = 256 edges (CSR-sorted by dst).
// hidden (bf16 hi/lo) -> wmma m16n16k16 (3 products, K=64), 4 passes
// of 16 channels x 4 groups -> Dbuf (col-major) -> combine ->
// warp-segmented scan -> tail atomics.
// ============================================================
#define O_W1T   0                       // 512 f32 = 2 KB (pad to 4 KB)
#define O_BHI   4096                    // [64][256] bf16 = 32 KB
#define O_BLO   (O_BHI + 32768)
#define O_AHI   (O_BLO + 32768)         // [64][256] bf16 (k-major, col = edge)
#define O_ALO   (O_AHI + 32768)
#define O_DBUF  (O_ALO + 32768)         // [64 cols][256 edges] f32 = 64 KB
#define EK_SMEM (O_DBUF + 65536)        // 200704 B

__global__ void __launch_bounds__(256, 1) edge_wmma_kernel(
    const float* __restrict__ ef, const float* __restrict__ ea1,
    const float* __restrict__ cut, const float* __restrict__ W1,
    const float* __restrict__ W2) {
    extern __shared__ char smem[];
    float* sW1t = (float*)(smem + O_W1T);
    __nv_bfloat16* sBhi = (__nv_bfloat16*)(smem + O_BHI);
    __nv_bfloat16* sBlo = (__nv_bfloat16*)(smem + O_BLO);
    __nv_bfloat16* sAhi = (__nv_bfloat16*)(smem + O_AHI);
    __nv_bfloat16* sAlo = (__nv_bfloat16*)(smem + O_ALO);
    float* Dbuf = (float*)(smem + O_DBUF);
    const int tid = threadIdx.x, wid = tid >> 5, lane = tid & 31;
    const unsigned FULL = 0xffffffffu;

    // W1 transposed: sW1t[h*8 + r] = W1[r*64 + h]
    for (int i = tid; i < 512; i += 256) {
        int r = i >> 6, h = i & 63;
        sW1t[h * 8 + r] = W1[i];
    }
    // B = W2 [64][256] hi/lo (same layout as input)
    for (int i = tid; i < 16384; i += 256) {
        float v = W2[i];
        __nv_bfloat16 bh = __float2bfloat16(v);
        sBhi[i] = bh;
        sBlo[i] = __float2bfloat16(v - __bfloat162float(bh));
    }
    __syncthreads();

    typedef wmma::fragment<wmma::matrix_a, 16, 16, 16, __nv_bfloat16,
                           wmma::col_major> FragA;
    typedef wmma::fragment<wmma::matrix_b, 16, 16, 16, __nv_bfloat16,
                           wmma::row_major> FragB;
    typedef wmma::fragment<wmma::accumulator, 16, 16, 16, float> FragC;

    for (int tile = blockIdx.x; tile < NT; tile += gridDim.x) {
        const int slot = tile * ETILE + tid;
        const int ee  = g_perm[slot];
        const int src = g_srcs[slot];
        const int dst = g_dsts[slot];
        const float cu = cut[ee];
        const float sx = ea1[ee * 3], sy = ea1[ee * 3 + 1], sz = ea1[ee * 3 + 2];
        const float4 fa = *(const float4*)(ef + (size_t)ee * 8);
        const float4 fb = *(const float4*)(ef + (size_t)ee * 8 + 4);

        // hidden = silu(ef @ W1), bf16 hi/lo, column tid of A^T [64 k][256 m]
#pragma unroll 4
        for (int h = 0; h < 64; h++) {
            const float4 w0 = *(const float4*)(sW1t + h * 8);
            const float4 w1 = *(const float4*)(sW1t + h * 8 + 4);
            float a = fa.x * w0.x + fa.y * w0.y + fa.z * w0.z + fa.w * w0.w
                    + fb.x * w1.x + fb.y * w1.y + fb.z * w1.z + fb.w * w1.w;
            a = a / (1.f + __expf(-a));
            __nv_bfloat16 ah = __float2bfloat16(a);
            sAhi[h * 256 + tid] = ah;
            sAlo[h * 256 + tid] = __float2bfloat16(a - __bfloat162float(ah));
        }

        // segment structure by dst (edges sorted by dst globally)
        const int pd = __shfl_up_sync(FULL, dst, 1);
        const bool head = (lane == 0) || (dst != pd);
        int segs = head ? lane : 0;
#pragma unroll
        for (int d = 1; d < 32; d <<= 1) {
            int u = __shfl_up_sync(FULL, segs, d);
            if (lane >= d) segs = max(segs, u);
        }
        const int nh = __shfl_down_sync(FULL, head ? 1 : 0, 1);
        const bool tail = (lane == 31) || (nh != 0);
        __syncthreads();

        // 4 passes of 16 channels (x 4 path groups each)
        for (int ch = 0; ch < 4; ch++) {
            FragC acc[2][4];
#pragma unroll
            for (int i = 0; i < 2; i++)
#pragma unroll
                for (int g = 0; g < 4; g++)
                    wmma::fill_fragment(acc[i][g], 0.f);

#pragma unroll
            for (int k = 0; k < 4; k++) {
                FragA ahi[2], alo[2];
#pragma unroll
                for (int i = 0; i < 2; i++) {
                    const int m0 = (wid * 2 + i) * 16;
                    wmma::load_matrix_sync(ahi[i], sAhi + k * 16 * 256 + m0, 256);
                    wmma::load_matrix_sync(alo[i], sAlo + k * 16 * 256 + m0, 256);
                }
#pragma unroll
                for (int g = 0; g < 4; g++) {
                    FragB bhi, blo;
                    const int n0 = g * 64 + ch * 16;
                    wmma::load_matrix_sync(bhi, sBhi + k * 16 * 256 + n0, 256);
                    wmma::load_matrix_sync(blo, sBlo + k * 16 * 256 + n0, 256);
#pragma unroll
                    for (int i = 0; i < 2; i++) {
                        wmma::mma_sync(acc[i][g], ahi[i], bhi, acc[i][g]);
                        wmma::mma_sync(acc[i][g], alo[i], bhi, acc[i][g]);
                        wmma::mma_sync(acc[i][g], ahi[i], blo, acc[i][g]);
                    }
                }
            }
            // store col-major: Dbuf[(g*16+j)*256 + edge]
#pragma unroll
            for (int i = 0; i < 2; i++)
#pragma unroll
                for (int g = 0; g < 4; g++)
                    wmma::store_matrix_sync(
                        Dbuf + (g * 16) * 256 + (wid * 2 + i) * 16,
                        acc[i][g], 256, wmma::mem_col_major);
            __syncthreads();

            // combine these 16 channels; thread = edge
            const float* p0 = g_h0 + (size_t)src * 64 + ch * 16;
            const float* p1 = g_h1 + (size_t)src * 192 + ch * 16;
            float* T0p = g_T0 + (size_t)dst * 64 + ch * 16;
            float* T1p = g_T1 + (size_t)dst * 192 + ch * 16;
#pragma unroll
            for (int q = 0; q < 4; q++) {
                const float4 vA = *(const float4*)(p0 + 4 * q);
                const float4 vX = *(const float4*)(p1 + 4 * q);
                const float4 vY = *(const float4*)(p1 + 64 + 4 * q);
                const float4 vZ = *(const float4*)(p1 + 128 + 4 * q);
                const float h0a[4] = {vA.x, vA.y, vA.z, vA.w};
                const float hxa[4] = {vX.x, vX.y, vX.z, vX.w};
                const float hya[4] = {vY.x, vY.y, vY.z, vY.w};
                const float hza[4] = {vZ.x, vZ.y, vZ.z, vZ.w};
#pragma unroll
                for (int j4 = 0; j4 < 4; j4++) {
                    const int j = q * 4 + j4;
                    const float w00 = Dbuf[j * 256 + tid];
                    const float w11 = Dbuf[(16 + j) * 256 + tid];
                    const float w01 = Dbuf[(32 + j) * 256 + tid];
                    const float w10 = Dbuf[(48 + j) * 256 + tid];
                    const float dotv = hxa[j4] * sx + hya[j4] * sy + hza[j4] * sz;
                    float m0 = (w00 * h0a[j4] + w11 * dotv) * cu;
                    const float pp = w01 * h0a[j4] * cu;
                    const float qq = w10 * cu;
                    float mx = pp * sx + qq * hxa[j4];
                    float my = pp * sy + qq * hya[j4];
                    float mz = pp * sz + qq * hza[j4];
                    m0 = segsum(m0, segs, lane);
                    mx = segsum(mx, segs, lane);
                    my = segsum(my, segs, lane);
                    mz = segsum(mz, segs, lane);
                    if (tail) {
                        atomicAdd(T0p + j, m0);
                        atomicAdd(T1p + j, mx);
                        atomicAdd(T1p + 64 + j, my);
                        atomicAdd(T1p + 128 + j, mz);
                    }
                }
            }
            __syncthreads();
        }
    }
}

// ============================================================
// Epilogue 0: out[n][0:64] = mi0 ; out[n][256:320] = mi0 @ Wsc0[s]
// (applies the 1/16 normalizer here)
// ============================================================
__global__ void __launch_bounds__(256) node0_kernel(
    const float* __restrict__ attrs, const float* __restrict__ Wsc0,
    float* __restrict__ out) {
    extern __shared__ float sm[];
    float* sW  = sm;
    float* sMi = sm + 40960;
    const int tid = threadIdx.x, wid = tid >> 5, lane = tid & 31;
    const int l2 = 2 * lane;
    const unsigned FULL = 0xffffffffu;
    for (int i = tid; i < SS * CC * CC; i += 256) sW[i] = Wsc0[i];
    __syncthreads();

    const ull inv = dup2(1.f / 16.f);
    float* sMiW = sMi + wid * 64;
    for (int node = blockIdx.x * 8 + wid; node < NN; node += gridDim.x * 8) {
        const ull mi = mul2(*(const ull*)(g_T0 + (size_t)node * 64 + l2), inv);
        *(ull*)(sMiW + l2) = mi;
        const float av = (lane < SS) ? attrs[(size_t)node * SS + lane] : 0.f;
        const unsigned bal = __ballot_sync(FULL, av > 0.5f);
        int s = __ffs(bal) - 1;
        if (s < 0) s = 0;
        __syncwarp();
        const float* W = sW + s * 4096 + l2;
        ull A = 0;
#pragma unroll 8
        for (int c = 0; c < 64; c++)
            fma2(A, dup2(sMiW[c]), *(const ull*)(W + c * 64));
        float* orow = out + (size_t)node * 512;
        *(ull*)(orow + l2)       = mi;
        *(ull*)(orow + 256 + l2) = A;
        __syncwarp();
    }
}

// ============================================================
// Epilogue 1: out[n][64+c*3+i] = mi1 ; out[n][320+o*3+i] = res1
// ============================================================
__global__ void __launch_bounds__(256) node1_kernel(
    const float* __restrict__ attrs, const float* __restrict__ Wsc1,
    float* __restrict__ out) {
    extern __shared__ float sm[];
    float* sW  = sm;
    float* sMi = sm + 40960;
    const int tid = threadIdx.x, wid = tid >> 5, lane = tid & 31;
    const int l2 = 2 * lane;
    const unsigned FULL = 0xffffffffu;
    for (int i = tid; i < SS * CC * CC; i += 256) sW[i] = Wsc1[i];
    __syncthreads();

    const ull inv = dup2(1.f / 16.f);
    float* sMiW = sMi + wid * 192;
    for (int node = blockIdx.x * 8 + wid; node < NN; node += gridDim.x * 8) {
        const float* t1 = g_T1 + (size_t)node * 192 + l2;
        const ull mx = mul2(*(const ull*)t1, inv);
        const ull my = mul2(*(const ull*)(t1 + 64), inv);
        const ull mz = mul2(*(const ull*)(t1 + 128), inv);
        *(ull*)(sMiW + l2)       = mx;
        *(ull*)(sMiW + 64 + l2)  = my;
        *(ull*)(sMiW + 128 + l2) = mz;
        const float av = (lane < SS) ? attrs[(size_t)node * SS + lane] : 0.f;
        const unsigned bal = __ballot_sync(FULL, av > 0.5f);
        int s = __ffs(bal) - 1;
        if (s < 0) s = 0;
        __syncwarp();
        const float* W = sW + s * 4096 + l2;
        ull A0 = 0, A1 = 0, A2 = 0;
#pragma unroll 8
        for (int c = 0; c < 64; c++) {
            const ull wv = *(const ull*)(W + c * 64);
            fma2(A0, dup2(sMiW[c]), wv);
            fma2(A1, dup2(sMiW[64 + c]), wv);
            fma2(A2, dup2(sMiW[128 + c]), wv);
        }
        float u0, u1, v0, v1, q0, q1;
        unpack2(mx, u0, u1); unpack2(my, v0, v1); unpack2(mz, q0, q1);
        float* orow = out + (size_t)node * 512;
        float* om = orow + 64 + 6 * lane;
        om[0] = u0; om[1] = v0; om[2] = q0;
        om[3] = u1; om[4] = v1; om[5] = q1;
        unpack2(A0, u0, u1); unpack2(A1, v0, v1); unpack2(A2, q0, q1);
        float* orr = orow + 320 + 6 * lane;
        orr[0] = u0; orr[1] = v0; orr[2] = q0;
        orr[3] = u1; orr[4] = v1; orr[5] = q1;
        __syncwarp();
    }
}

// ============================================================
extern "C" void kernel_launch(void* const* d_in, const int* in_sizes, int n_in,
                              void* d_out, int out_size) {
    const float* nf0   = (const float*)d_in[0];
    const float* nf1   = (const float*)d_in[1];
    const float* attrs = (const float*)d_in[2];
    const float* ef    = (const float*)d_in[3];
    const float* ea1   = (const float*)d_in[4];
    const float* cut   = (const float*)d_in[5];
    const float* Wup0  = (const float*)d_in[6];
    const float* Wup1  = (const float*)d_in[7];
    const float* W1    = (const float*)d_in[8];
    const float* W2    = (const float*)d_in[9];
    const float* Wsc0  = (const float*)d_in[10];
    const float* Wsc1  = (const float*)d_in[11];
    // d_in[12], d_in[13]: Q0/Q1 identity projectors (no-op)
    const int*   ei    = (const int*)d_in[14];
    float* out = (float*)d_out;

    const int up_smem = 16384 * 4;
    const int c0_smem = (40960 + 512) * 4;
    const int c1_smem = (40960 + 1536) * 4;
    cudaFuncSetAttribute(up_kernel,        cudaFuncAttributeMaxDynamicSharedMemorySize, up_smem);
    cudaFuncSetAttribute(edge_wmma_kernel, cudaFuncAttributeMaxDynamicSharedMemorySize, EK_SMEM);
    cudaFuncSetAttribute(node0_kernel,     cudaFuncAttributeMaxDynamicSharedMemorySize, c0_smem);
    cudaFuncSetAttribute(node1_kernel,     cudaFuncAttributeMaxDynamicSharedMemorySize, c1_smem);

    zero_kernel<<<9375, 256>>>();
    hist_kernel<<<EE / 256, 256>>>(ei);
    scan_kernel<<<1, 1024>>>();
    scatter_kernel<<<EE / 256, 256>>>(ei);
    up_kernel<<<(NN + 31) / 32, 256, up_smem>>>(nf0, nf1, Wup0, Wup1);
    edge_wmma_kernel<<<304, 256, EK_SMEM>>>(ef, ea1, cut, W1, W2);
    node0_kernel<<<296, 256, c0_smem>>>(attrs, Wsc0, out);
    node1_kernel<<<296, 256, c1_smem>>>(attrs, Wsc1, out);
}

// round 10
// speedup vs baseline: 1.6099x; 1.6099x over previous
#include <cuda_runtime.h>
#include <math.h>

#define NN 50000
#define EE 800000
#define CC 64
#define SS 10
#define HH 64

typedef unsigned long long ull;

// -------- scratch (static device globals; no allocation) --------
__device__ float g_h0[NN * CC];        // up-projected scalars   [n][c]
__device__ float g_h1[NN * 3 * CC];    // up-projected vectors   [n][i][c]
__device__ float g_T0[NN * CC];        // node messages (already /16)
__device__ float g_T1[NN * 3 * CC];
__device__ float g_hid[(EE + 8) * HH]; // silu(ef@W1), CSR-sorted order (+pad)
__device__ int   g_deg[NN];
__device__ int   g_off[NN + 1];
__device__ int   g_cur[NN];
__device__ int   g_perm[EE];

// -------- f32x2 packed math helpers (sm_100+) --------
__device__ __forceinline__ ull dup2(float x) {
    ull r; asm("mov.b64 %0, {%1, %1};" : "=l"(r) : "r"(__float_as_uint(x)));
    return r;
}
__device__ __forceinline__ void fma2(ull& d, ull a, ull b) {
    asm("fma.rn.f32x2 %0, %1, %2, %0;" : "+l"(d) : "l"(a), "l"(b));
}
__device__ __forceinline__ ull mul2(ull a, ull b) {
    ull d; asm("mul.rn.f32x2 %0, %1, %2;" : "=l"(d) : "l"(a), "l"(b));
    return d;
}
__device__ __forceinline__ void unpack2(ull v, float& lo, float& hi) {
    unsigned int a, b;
    asm("mov.b64 {%0, %1}, %2;" : "=r"(a), "=r"(b) : "l"(v));
    lo = __uint_as_float(a); hi = __uint_as_float(b);
}

// ============================================================
// CSR build
// ============================================================
__global__ void zero_deg_kernel() {
    int i = blockIdx.x * 256 + threadIdx.x;
    if (i < NN) g_deg[i] = 0;
}

__global__ void hist_kernel(const int* __restrict__ ei) {
    int e = blockIdx.x * 256 + threadIdx.x;   // E = 3125*256 exact
    atomicAdd(&g_deg[ei[EE + e]], 1);
}

__global__ void __launch_bounds__(1024) scan_kernel() {
    __shared__ int sp[1024];
    const int t = threadIdx.x;
    const int CH = (NN + 1023) / 1024;       // 49
    const int i0 = t * CH;
    const int i1 = min(i0 + CH, NN);
    int part = 0;
    for (int i = i0; i < i1; i++) part += g_deg[i];
    sp[t] = part;
    __syncthreads();
    for (int off = 1; off < 1024; off <<= 1) {
        int v = (t >= off) ? sp[t - off] : 0;
        __syncthreads();
        sp[t] += v;
        __syncthreads();
    }
    int run = sp[t] - part;                  // exclusive base
    for (int i = i0; i < i1; i++) {
        g_off[i] = run;
        g_cur[i] = run;
        run += g_deg[i];
    }
    if (t == 0) g_off[NN] = EE;
}

__global__ void scatter_kernel(const int* __restrict__ ei) {
    int e = blockIdx.x * 256 + threadIdx.x;
    int pos = atomicAdd(&g_cur[ei[EE + e]], 1);
    g_perm[pos] = e;
}

// ============================================================
// Hidden precompute: g_hid[slot] = silu(ef[perm[slot]] @ W1)
// (sorted order so the node kernel reads contiguously)
// ============================================================
__global__ void __launch_bounds__(128) hidden_kernel(
    const float* __restrict__ ef, const float* __restrict__ W1) {
    __shared__ float sW1t[512];        // transposed [h][8]
    __shared__ float sbuf[128 * 68];   // per-thread hidden row (padded)
    const int tid = threadIdx.x, wid = tid >> 5, lane = tid & 31;

    for (int i = tid; i < 512; i += 128) {
        int r = i >> 6, h = i & 63;
        sW1t[h * 8 + r] = W1[i];
    }
    __syncthreads();

    const int slot0 = blockIdx.x * 128;
    const int ee = g_perm[slot0 + tid];
    const float4 fa = *(const float4*)(ef + (size_t)ee * 8);
    const float4 fb = *(const float4*)(ef + (size_t)ee * 8 + 4);
    float* row = sbuf + tid * 68;
#pragma unroll 4
    for (int h = 0; h < 64; h++) {
        const float4 w0 = *(const float4*)(sW1t + h * 8);
        const float4 w1 = *(const float4*)(sW1t + h * 8 + 4);
        float a = fa.x * w0.x + fa.y * w0.y + fa.z * w0.z + fa.w * w0.w
                + fb.x * w1.x + fb.y * w1.y + fb.z * w1.z + fb.w * w1.w;
        row[h] = a / (1.f + __expf(-a));
    }
    __syncwarp();

    // coalesced write: each warp writes its own 32 edge rows
    const float* srcp = sbuf + (wid * 32) * 68;
    float* dstp = g_hid + (size_t)(slot0 + wid * 32) * 64;
#pragma unroll 4
    for (int e = 0; e < 32; e++) {
        const float2 v = *(const float2*)(srcp + e * 68 + 2 * lane);
        *(float2*)(dstp + e * 64 + 2 * lane) = v;
    }
}

// ============================================================
// Up-projection: h0 = nf0 @ Wup0 ; g_h1[n][i][o] = sum_c nf1[n,c,i] Wup1[c,o]
// ============================================================
__global__ void __launch_bounds__(256) up_kernel(
    const float* __restrict__ nf0, const float* __restrict__ nf1,
    const float* __restrict__ Wup0, const float* __restrict__ Wup1) {
    extern __shared__ float sm[];
    float* sW0  = sm;
    float* sW1m = sm + 4096;
    float* s0   = sm + 8192;
    float* s1   = sm + 10240;
    const int tid  = threadIdx.x;
    const int base = blockIdx.x * 32;

    for (int i = tid; i < 4096; i += 256) { sW0[i] = Wup0[i]; sW1m[i] = Wup1[i]; }
    for (int i = tid; i < 2048; i += 256) {
        size_t g = (size_t)base * 64 + i;
        s0[i] = (g < (size_t)NN * 64) ? nf0[g] : 0.f;
    }
    for (int i = tid; i < 6144; i += 256) {
        size_t g = (size_t)base * 192 + i;
        s1[i] = (g < (size_t)NN * 192) ? nf1[g] : 0.f;
    }
    __syncthreads();

    const int o = tid & 63, ng = tid >> 6;
    for (int nl = ng; nl < 32; nl += 4) {
        const int n = base + nl;
        if (n >= NN) break;
        float a = 0.f;
#pragma unroll
        for (int c = 0; c < 64; c++) a += s0[nl * 64 + c] * sW0[c * 64 + o];
        g_h0[(size_t)n * 64 + o] = a;
#pragma unroll
        for (int i3 = 0; i3 < 3; i3++) {
            float b = 0.f;
#pragma unroll 16
            for (int c = 0; c < 64; c++)
                b += s1[nl * 192 + c * 3 + i3] * sW1m[c * 64 + o];
            g_h1[((size_t)n * 3 + i3) * 64 + o] = b;
        }
    }
}

// ============================================================
// Fused node-centric kernel: warp per node, NJ-edge batches.
// Hidden read from g_hid (precomputed, sorted); W2 GEMV amortized
// over NJ edges; gathers register-prefetched; no atomics.
// ============================================================
__device__ __forceinline__ void gather4(
    const int src_, const int j0, ull* gh0, ull* ghx, ull* ghy, ull* ghz,
    const int l2) {
#pragma unroll
    for (int j = 0; j < 4; j++) {
        const int sj = __shfl_sync(0xffffffffu, src_, j0 + j);
        const float* p0 = g_h0 + (size_t)sj * 64 + l2;
        const float* p1 = g_h1 + (size_t)sj * 192 + l2;
        gh0[j] = *(const ull*)p0;
        ghx[j] = *(const ull*)p1;
        ghy[j] = *(const ull*)(p1 + 64);
        ghz[j] = *(const ull*)(p1 + 128);
    }
}

__device__ __forceinline__ void combine4(
    const float cu_, const float sx_, const float sy_, const float sz_,
    const int j0, const ull* gh0, const ull* ghx, const ull* ghy,
    const ull* ghz, const ull* w00, const ull* w11, const ull* w01,
    const ull* w10, ull& m0, ull& m1x, ull& m1y, ull& m1z) {
    const unsigned FULL = 0xffffffffu;
#pragma unroll
    for (int j = 0; j < 4; j++) {
        const float cub = __shfl_sync(FULL, cu_, j0 + j);
        const float sxb = __shfl_sync(FULL, sx_, j0 + j);
        const float syb = __shfl_sync(FULL, sy_, j0 + j);
        const float szb = __shfl_sync(FULL, sz_, j0 + j);
        ull d = mul2(ghx[j], dup2(sxb));
        fma2(d, ghy[j], dup2(syb));
        fma2(d, ghz[j], dup2(szb));
        ull t = mul2(w00[j0 + j], gh0[j]);
        fma2(t, w11[j0 + j], d);
        fma2(m0, t, dup2(cub));
        ull p = mul2(w01[j0 + j], gh0[j]);
        fma2(m1x, p, dup2(cub * sxb));
        fma2(m1y, p, dup2(cub * syb));
        fma2(m1z, p, dup2(cub * szb));
        ull q = mul2(w10[j0 + j], dup2(cub));
        fma2(m1x, q, ghx[j]);
        fma2(m1y, q, ghy[j]);
        fma2(m1z, q, ghz[j]);
    }
}

template<int NJ>
__device__ __forceinline__ void process_batch(
    const int b, const int end, const int lane,
    const float* __restrict__ sW2, float* __restrict__ sH,
    const float* __restrict__ ea1, const float* __restrict__ cut,
    const int* __restrict__ ei,
    ull& m0, ull& m1x, ull& m1y, ull& m1z) {
    const int l2 = 2 * lane;

    // lanes 0..NJ-1 stage edge meta (padded slots: cu=0 kills contributions)
    int src_ = 0;
    float cu_ = 0.f, sx_ = 0.f, sy_ = 0.f, sz_ = 0.f;
    if (lane < NJ) {
        const int idx = b + lane;
        const int ee  = g_perm[idx < end ? idx : b];
        src_ = ei[ee];
        cu_  = (idx < end) ? cut[ee] : 0.f;
        sx_  = ea1[ee * 3];
        sy_  = ea1[ee * 3 + 1];
        sz_  = ea1[ee * 3 + 2];
    }

    // stage hidden (precomputed, sorted, contiguous) into smem
    {
        const int j = lane >> 2, c4 = (lane & 3) * 16;
        if (j < NJ) {
            const float* gp = g_hid + (size_t)(b + j) * 64 + c4;
            float* sp = sH + j * 68 + c4;
#pragma unroll
            for (int k = 0; k < 4; k++)
                *(float4*)(sp + 4 * k) = *(const float4*)(gp + 4 * k);
        }
    }
    __syncwarp();

    // prefetch gathers for first half (hidden under the GEMV below)
    ull gh0a[4], ghxa[4], ghya[4], ghza[4];
    gather4(src_, 0, gh0a, ghxa, ghya, ghza, l2);

    // w = hid @ W2; lane owns channel pair (2l, 2l+1) of each of 4 groups
    ull w00[NJ], w11[NJ], w01[NJ], w10[NJ];
#pragma unroll
    for (int j = 0; j < NJ; j++) { w00[j] = 0; w11[j] = 0; w01[j] = 0; w10[j] = 0; }
    const float* bp = sW2 + l2;
#pragma unroll 1
    for (int h = 0; h < 64; h += 2) {
        const float* r0 = bp + h * 256;
        const float* r1 = r0 + 256;
        const ull b00a = *(const ull*)r0,         b00b = *(const ull*)r1;
        const ull b11a = *(const ull*)(r0 + 64),  b11b = *(const ull*)(r1 + 64);
        const ull b01a = *(const ull*)(r0 + 128), b01b = *(const ull*)(r1 + 128);
        const ull b10a = *(const ull*)(r0 + 192), b10b = *(const ull*)(r1 + 192);
#pragma unroll
        for (int j = 0; j < NJ; j++) {
            const float2 hv = *(const float2*)(sH + j * 68 + h);  // broadcast
            const ull ha = dup2(hv.x), hb = dup2(hv.y);
            fma2(w00[j], ha, b00a); fma2(w00[j], hb, b00b);
            fma2(w11[j], ha, b11a); fma2(w11[j], hb, b11b);
            fma2(w01[j], ha, b01a); fma2(w01[j], hb, b01b);
            fma2(w10[j], ha, b10a); fma2(w10[j], hb, b10b);
        }
    }

    if constexpr (NJ == 8) {
        // prefetch second half; its latency hides under first combine
        ull gh0b[4], ghxb[4], ghyb[4], ghzb[4];
        gather4(src_, 4, gh0b, ghxb, ghyb, ghzb, l2);
        combine4(cu_, sx_, sy_, sz_, 0, gh0a, ghxa, ghya, ghza,
                 w00, w11, w01, w10, m0, m1x, m1y, m1z);
        combine4(cu_, sx_, sy_, sz_, 4, gh0b, ghxb, ghyb, ghzb,
                 w00, w11, w01, w10, m0, m1x, m1y, m1z);
    } else {
        combine4(cu_, sx_, sy_, sz_, 0, gh0a, ghxa, ghya, ghza,
                 w00, w11, w01, w10, m0, m1x, m1y, m1z);
    }
    __syncwarp();   // protect sH before next batch overwrites
}

__global__ void __launch_bounds__(128, 3) node_kernel(
    const float* __restrict__ ea1, const float* __restrict__ cut,
    const float* __restrict__ W2, const int* __restrict__ ei) {
    extern __shared__ float sm[];
    float* sW2 = sm;                           // 16384 floats
    float* sHAll = sm + 16384;                 // 4 warps * 544 floats
    const int tid = threadIdx.x;
    for (int i = tid; i < 16384; i += 128) sW2[i] = W2[i];
    __syncthreads();

    const int wid = tid >> 5, lane = tid & 31;
    float* sH = sHAll + wid * 544;             // 8 rows * 68 floats
    const int l2 = 2 * lane;

    for (int node = blockIdx.x * 4 + wid; node < NN; node += gridDim.x * 4) {
        const int beg = g_off[node];
        const int end = g_off[node + 1];
        ull m0 = 0, m1x = 0, m1y = 0, m1z = 0;

        int b = beg;
        for (; b + 8 <= end; b += 8)
            process_batch<8>(b, end, lane, sW2, sH, ea1, cut, ei,
                             m0, m1x, m1y, m1z);
        const int rem = end - b;
        if (rem > 4)
            process_batch<8>(b, end, lane, sW2, sH, ea1, cut, ei,
                             m0, m1x, m1y, m1z);
        else if (rem > 0)
            process_batch<4>(b, end, lane, sW2, sH, ea1, cut, ei,
                             m0, m1x, m1y, m1z);

        const ull inv = dup2(1.f / 16.f);
        *(ull*)(g_T0 + (size_t)node * 64 + l2) = mul2(m0, inv);
        float* t1 = g_T1 + (size_t)node * 192 + l2;
        *(ull*)t1         = mul2(m1x, inv);
        *(ull*)(t1 + 64)  = mul2(m1y, inv);
        *(ull*)(t1 + 128) = mul2(m1z, inv);
    }
}

// ============================================================
// Epilogue 0: out[n][0:64] = mi0 ; out[n][256:320] = mi0 @ Wsc0[s]
// ============================================================
__global__ void __launch_bounds__(256) node0_kernel(
    const float* __restrict__ attrs, const float* __restrict__ Wsc0,
    float* __restrict__ out) {
    extern __shared__ float sm[];
    float* sW  = sm;              // 40960
    float* sMi = sm + 40960;      // 8 warps * 64
    const int tid = threadIdx.x, wid = tid >> 5, lane = tid & 31;
    const int l2 = 2 * lane;
    const unsigned FULL = 0xffffffffu;
    for (int i = tid; i < SS * CC * CC; i += 256) sW[i] = Wsc0[i];
    __syncthreads();

    float* sMiW = sMi + wid * 64;
    for (int node = blockIdx.x * 8 + wid; node < NN; node += gridDim.x * 8) {
        const ull mi = *(const ull*)(g_T0 + (size_t)node * 64 + l2);
        *(ull*)(sMiW + l2) = mi;
        const float av = (lane < SS) ? attrs[(size_t)node * SS + lane] : 0.f;
        const unsigned bal = __ballot_sync(FULL, av > 0.5f);
        int s = __ffs(bal) - 1;
        if (s < 0) s = 0;
        __syncwarp();
        const float* W = sW + s * 4096 + l2;
        ull A = 0;
#pragma unroll 8
        for (int c = 0; c < 64; c++)
            fma2(A, dup2(sMiW[c]), *(const ull*)(W + c * 64));
        float* orow = out + (size_t)node * 512;
        *(ull*)(orow + l2)       = mi;
        *(ull*)(orow + 256 + l2) = A;
        __syncwarp();
    }
}

// ============================================================
// Epilogue 1: out[n][64+c*3+i] = mi1 ; out[n][320+o*3+i] = res1
// ============================================================
__global__ void __launch_bounds__(256) node1_kernel(
    const float* __restrict__ attrs, const float* __restrict__ Wsc1,
    float* __restrict__ out) {
    extern __shared__ float sm[];
    float* sW  = sm;              // 40960
    float* sMi = sm + 40960;      // 8 warps * 192
    const int tid = threadIdx.x, wid = tid >> 5, lane = tid & 31;
    const int l2 = 2 * lane;
    const unsigned FULL = 0xffffffffu;
    for (int i = tid; i < SS * CC * CC; i += 256) sW[i] = Wsc1[i];
    __syncthreads();

    float* sMiW = sMi + wid * 192;
    for (int node = blockIdx.x * 8 + wid; node < NN; node += gridDim.x * 8) {
        const float* t1 = g_T1 + (size_t)node * 192 + l2;
        const ull mx = *(const ull*)t1;
        const ull my = *(const ull*)(t1 + 64);
        const ull mz = *(const ull*)(t1 + 128);
        *(ull*)(sMiW + l2)        = mx;
        *(ull*)(sMiW + 64 + l2)   = my;
        *(ull*)(sMiW + 128 + l2)  = mz;
        const float av = (lane < SS) ? attrs[(size_t)node * SS + lane] : 0.f;
        const unsigned bal = __ballot_sync(FULL, av > 0.5f);
        int s = __ffs(bal) - 1;
        if (s < 0) s = 0;
        __syncwarp();
        const float* W = sW + s * 4096 + l2;
        ull A0 = 0, A1 = 0, A2 = 0;
#pragma unroll 8
        for (int c = 0; c < 64; c++) {
            const ull wv = *(const ull*)(W + c * 64);
            fma2(A0, dup2(sMiW[c]), wv);
            fma2(A1, dup2(sMiW[64 + c]), wv);
            fma2(A2, dup2(sMiW[128 + c]), wv);
        }
        float u0, u1, v0, v1, q0, q1;
        unpack2(mx, u0, u1); unpack2(my, v0, v1); unpack2(mz, q0, q1);
        float* orow = out + (size_t)node * 512;
        float* om = orow + 64 + 6 * lane;
        om[0] = u0; om[1] = v0; om[2] = q0;
        om[3] = u1; om[4] = v1; om[5] = q1;
        unpack2(A0, u0, u1); unpack2(A1, v0, v1); unpack2(A2, q0, q1);
        float* orr = orow + 320 + 6 * lane;
        orr[0] = u0; orr[1] = v0; orr[2] = q0;
        orr[3] = u1; orr[4] = v1; orr[5] = q1;
        __syncwarp();
    }
}

// ============================================================
extern "C" void kernel_launch(void* const* d_in, const int* in_sizes, int n_in,
                              void* d_out, int out_size) {
    const float* nf0   = (const float*)d_in[0];
    const float* nf1   = (const float*)d_in[1];
    const float* attrs = (const float*)d_in[2];
    const float* ef    = (const float*)d_in[3];
    const float* ea1   = (const float*)d_in[4];
    const float* cut   = (const float*)d_in[5];
    const float* Wup0  = (const float*)d_in[6];
    const float* Wup1  = (const float*)d_in[7];
    const float* W1    = (const float*)d_in[8];
    const float* W2    = (const float*)d_in[9];
    const float* Wsc0  = (const float*)d_in[10];
    const float* Wsc1  = (const float*)d_in[11];
    // d_in[12], d_in[13] are Q0/Q1 identity projectors (no-op)
    const int*   ei    = (const int*)d_in[14];
    float* out = (float*)d_out;

    const int up_smem   = 16384 * 4;                        // 64 KB
    const int node_smem = (16384 + 4 * 544) * 4;            // 74.2 KB -> 3 CTA/SM
    const int c0_smem   = (40960 + 512) * 4;                // 166 KB
    const int c1_smem   = (40960 + 1536) * 4;               // 170 KB
    cudaFuncSetAttribute(up_kernel,    cudaFuncAttributeMaxDynamicSharedMemorySize, up_smem);
    cudaFuncSetAttribute(node_kernel,  cudaFuncAttributeMaxDynamicSharedMemorySize, node_smem);
    cudaFuncSetAttribute(node0_kernel, cudaFuncAttributeMaxDynamicSharedMemorySize, c0_smem);
    cudaFuncSetAttribute(node1_kernel, cudaFuncAttributeMaxDynamicSharedMemorySize, c1_smem);

    zero_deg_kernel<<<(NN + 255) / 256, 256>>>();
    hist_kernel<<<EE / 256, 256>>>(ei);
    scan_kernel<<<1, 1024>>>();
    scatter_kernel<<<EE / 256, 256>>>(ei);
    hidden_kernel<<<EE / 128, 128>>>(ef, W1);
    up_kernel<<<(NN + 31) / 32, 256, up_smem>>>(nf0, nf1, Wup0, Wup1);
    node_kernel<<<444, 128, node_smem>>>(ea1, cut, W2, ei);
    node0_kernel<<<296, 256, c0_smem>>>(attrs, Wsc0, out);
    node1_kernel<<<296, 256, c1_smem>>>(attrs, Wsc1, out);
}